// round 15
// baseline (speedup 1.0000x reference)
#include <cuda_runtime.h>
#include <math.h>
#include <stdint.h>

typedef unsigned long long u64;

static constexpr int B_  = 4;
static constexpr int L_  = 1024;
static constexpr int D_  = 768;
static constexpr int H_  = 12;
static constexpr int HD_ = 64;
static constexpr int TQ_ = 128;
static constexpr int TK_ = 128;
static constexpr int NCH_ = L_ / TK_;   // 8

// attn dynamic smem: pass1 Qh/Ql[128][68] + Kh/Kl[128][20] = 22528 floats
static constexpr int DYN_SMEM_BYTES = (2*128*68 + 2*128*20) * 4;   // 90112

// mma GEMM config
static constexpr int KT  = 16;          // k-tile
static constexpr int NKT = D_ / KT;     // 48
static constexpr int PAD = 20;          // floats per smem row (16 used)
static constexpr int STAGE_F = 128*PAD;             // floats per tile-stage
static constexpr int GEMM_SMEM = 8 * STAGE_F * 4;   // 2 stages x 4 arrays = 81920B

// ---------------- mma.sync helpers ----------------
__device__ __forceinline__ uint32_t smem_u32(const void* p) {
    uint32_t a;
    asm("{ .reg .u64 t; cvta.to.shared.u64 t, %1; cvt.u32.u64 %0, t; }"
        : "=r"(a) : "l"(p));
    return a;
}
__device__ __forceinline__ float tf32_rna(float x) {
    uint32_t r; asm("cvt.rna.tf32.f32 %0, %1;" : "=r"(r) : "f"(x));
    return __uint_as_float(r);
}
__device__ __forceinline__ void ldsm4(uint32_t r[4], uint32_t a) {
    asm volatile("ldmatrix.sync.aligned.m8n8.x4.shared.b16 {%0,%1,%2,%3}, [%4];"
        : "=r"(r[0]), "=r"(r[1]), "=r"(r[2]), "=r"(r[3]) : "r"(a));
}
__device__ __forceinline__ void ldsm2(uint32_t r[2], uint32_t a) {
    asm volatile("ldmatrix.sync.aligned.m8n8.x2.shared.b16 {%0,%1}, [%2];"
        : "=r"(r[0]), "=r"(r[1]) : "r"(a));
}
__device__ __forceinline__ void mma8(float c[4], const uint32_t a[4],
                                     const uint32_t b[2]) {
    asm volatile(
        "mma.sync.aligned.m16n8k8.row.col.f32.tf32.tf32.f32 "
        "{%0,%1,%2,%3}, {%4,%5,%6,%7}, {%8,%9}, {%0,%1,%2,%3};"
        : "+f"(c[0]), "+f"(c[1]), "+f"(c[2]), "+f"(c[3])
        : "r"(a[0]), "r"(a[1]), "r"(a[2]), "r"(a[3]), "r"(b[0]), "r"(b[1]));
}
// split a float4 into tf32 hi / fp32 residual lo
__device__ __forceinline__ void split4(float4 v, float4& h, float4& l) {
    h.x = tf32_rna(v.x); l.x = v.x - h.x;
    h.y = tf32_rna(v.y); l.y = v.y - h.y;
    h.z = tf32_rna(v.z); l.z = v.z - h.z;
    h.w = tf32_rna(v.w); l.w = v.w - h.w;
}

// ---------------- device scratch ----------------
__device__ float g_q[(size_t)B_ * L_ * D_];
__device__ float g_k[(size_t)B_ * L_ * D_];
__device__ float g_v[(size_t)B_ * L_ * D_];
__device__ float g_w[(size_t)B_ * L_ * D_];

// ---------------- split-tf32 mma GEMM, double-buffered -------------------
// 8 warps: 4 wy (m) x 2 wx (n); warp tile 32m x 64n. One barrier per k-tile.
__device__ __forceinline__ void mma_gemm_tile128(const float* __restrict__ A,
                                                 const float* __restrict__ W,
                                                 const float* __restrict__ bias,
                                                 float* __restrict__ C,
                                                 int m0, int n0)
{
    extern __shared__ float gsm[];
    float* Ah = gsm;                    // [2][128*PAD]
    float* Al = gsm + 2*STAGE_F;
    float* Bh = gsm + 4*STAGE_F;
    float* Bl = gsm + 6*STAGE_F;

    const int tid  = threadIdx.x;
    const int lane = tid & 31, wid = tid >> 5;
    const int wy = wid & 3, wx = wid >> 2;
    const int gid = lane >> 2, tig = lane & 3;

    const int rowL = tid >> 1, khL = (tid & 1) * 8;
    const float* Ap = A + (size_t)(m0 + rowL) * D_ + khL;
    const float* Wp = W + (size_t)(n0 + rowL) * D_ + khL;

    uint32_t aAh[2], aAl[2], aBh, aBl;
    {
        int r  = 32*wy + (lane & 7) + 8*((lane >> 3) & 1);
        int kc = 4 * (lane >> 4);
        aAh[0] = smem_u32(&Ah[r*PAD + kc]);
        aAh[1] = aAh[0] + 16*PAD*4;
        aAl[0] = smem_u32(&Al[r*PAD + kc]);
        aAl[1] = aAl[0] + 16*PAD*4;
        int rB  = 64*wx + (lane & 7);
        int kcB = 4 * ((lane >> 3) & 1);
        aBh = smem_u32(&Bh[rB*PAD + kcB]);
        aBl = smem_u32(&Bl[rB*PAD + kcB]);
    }

    float c[2][8][4] = {};

    // prologue: load + stage kt=0 into stage 0
    float4 va0 = *(const float4*)(Ap);
    float4 va1 = *(const float4*)(Ap + 4);
    float4 vb0 = *(const float4*)(Wp);
    float4 vb1 = *(const float4*)(Wp + 4);
    {
        float4 h, l;
        split4(va0, h, l);
        *(float4*)&Ah[rowL*PAD + khL] = h; *(float4*)&Al[rowL*PAD + khL] = l;
        split4(va1, h, l);
        *(float4*)&Ah[rowL*PAD + khL + 4] = h; *(float4*)&Al[rowL*PAD + khL + 4] = l;
        split4(vb0, h, l);
        *(float4*)&Bh[rowL*PAD + khL] = h; *(float4*)&Bl[rowL*PAD + khL] = l;
        split4(vb1, h, l);
        *(float4*)&Bh[rowL*PAD + khL + 4] = h; *(float4*)&Bl[rowL*PAD + khL + 4] = l;
    }
    __syncthreads();

    for (int kt = 0; kt < NKT; kt++) {
        if (kt + 1 < NKT) {
            va0 = *(const float4*)(Ap + (kt+1)*KT);
            va1 = *(const float4*)(Ap + (kt+1)*KT + 4);
            vb0 = *(const float4*)(Wp + (kt+1)*KT);
            vb1 = *(const float4*)(Wp + (kt+1)*KT + 4);
        }
        const uint32_t sboff = (uint32_t)((kt & 1) * STAGE_F * 4);
        #pragma unroll
        for (int k8 = 0; k8 < 2; k8++) {
            const uint32_t ko = sboff + (uint32_t)(k8 * 32);
            uint32_t ah[2][4], al[2][4];
            ldsm4(ah[0], aAh[0] + ko);
            ldsm4(ah[1], aAh[1] + ko);
            ldsm4(al[0], aAl[0] + ko);
            ldsm4(al[1], aAl[1] + ko);
            #pragma unroll
            for (int nj = 0; nj < 8; nj++) {
                uint32_t bh[2], bl[2];
                ldsm2(bh, aBh + (uint32_t)(nj*8*PAD*4) + ko);
                ldsm2(bl, aBl + (uint32_t)(nj*8*PAD*4) + ko);
                #pragma unroll
                for (int mi = 0; mi < 2; mi++) {
                    mma8(c[mi][nj], ah[mi], bh);
                    mma8(c[mi][nj], ah[mi], bl);
                    mma8(c[mi][nj], al[mi], bh);
                }
            }
        }
        if (kt + 1 < NKT) {
            const int st = ((kt + 1) & 1) * STAGE_F;
            float4 h, l;
            split4(va0, h, l);
            *(float4*)&Ah[st + rowL*PAD + khL] = h; *(float4*)&Al[st + rowL*PAD + khL] = l;
            split4(va1, h, l);
            *(float4*)&Ah[st + rowL*PAD + khL + 4] = h; *(float4*)&Al[st + rowL*PAD + khL + 4] = l;
            split4(vb0, h, l);
            *(float4*)&Bh[st + rowL*PAD + khL] = h; *(float4*)&Bl[st + rowL*PAD + khL] = l;
            split4(vb1, h, l);
            *(float4*)&Bh[st + rowL*PAD + khL + 4] = h; *(float4*)&Bl[st + rowL*PAD + khL + 4] = l;
        }
        __syncthreads();
    }

    #pragma unroll
    for (int mi = 0; mi < 2; mi++) {
        const int r0 = m0 + 32*wy + 16*mi + gid;
        #pragma unroll
        for (int nj = 0; nj < 8; nj++) {
            const int cc = n0 + 64*wx + 8*nj + 2*tig;
            float2 v0 = make_float2(c[mi][nj][0], c[mi][nj][1]);
            float2 v1 = make_float2(c[mi][nj][2], c[mi][nj][3]);
            if (bias) {
                float bx = bias[cc], by = bias[cc+1];
                v0.x += bx; v0.y += by;
                v1.x += bx; v1.y += by;
            }
            *(float2*)&C[(size_t)r0 * D_ + cc]       = v0;
            *(float2*)&C[(size_t)(r0 + 8) * D_ + cc] = v1;
        }
    }
}

__global__ __launch_bounds__(256)
void mma_qkv_kernel(const float* __restrict__ Aq, const float* __restrict__ Ak,
                    const float* __restrict__ Av,
                    const float* __restrict__ Wq, const float* __restrict__ Wk,
                    const float* __restrict__ Wv,
                    float* __restrict__ Cq, float* __restrict__ Ck,
                    float* __restrict__ Cv)
{
    const int sel = blockIdx.x / 6;
    const int n0  = (blockIdx.x % 6) * 128;
    const int m0  = blockIdx.y * 128;
    const float* A = (sel == 0) ? Aq : (sel == 1) ? Ak : Av;
    const float* W = (sel == 0) ? Wq : (sel == 1) ? Wk : Wv;
    float*       C = (sel == 0) ? Cq : (sel == 1) ? Ck : Cv;
    mma_gemm_tile128(A, W, nullptr, C, m0, n0);
}

__global__ __launch_bounds__(256)
void mma_proj_kernel(const float* __restrict__ A, const float* __restrict__ W,
                     const float* __restrict__ bias, float* __restrict__ C)
{
    mma_gemm_tile128(A, W, bias, C, blockIdx.y * 128, blockIdx.x * 128);
}

// ---------------- attention: all-mma (S pass + PV pass) ------------------
__global__ __launch_bounds__(256, 2)
void attn_kernel(const float* __restrict__ gq, const float* __restrict__ gk,
                 const float* __restrict__ gv,
                 const float* __restrict__ relk, const float* __restrict__ relv,
                 float* __restrict__ attn, float* __restrict__ gw)
{
    extern __shared__ float dsm[];
    // pass1 views
    float* Qh = dsm;                        // [128][68]
    float* Ql = dsm + 128*68;               // [128][68]
    float* Kh = dsm + 2*128*68;             // [128][20]
    float* Kl = dsm + 2*128*68 + 128*20;    // [128][20]
    // pass2 views (overlap)
    float* Es = dsm;                        // [128 m][132 k] row-major tf32
    float* Vs = dsm + 128*132;              // [64 k][68 d]   tf32 (half-chunk)

    __shared__ float sh_relk[7*HD_];
    __shared__ float sh_relv[7*HD_];
    __shared__ float sh_bias[TQ_*7];
    __shared__ float sh_rowmax[TQ_];
    __shared__ float sh_red[TQ_*2];
    __shared__ float sh_T[TQ_];
    __shared__ float sh_S0[TQ_];
    __shared__ float sh_S6[TQ_];
    __shared__ float sh_pmid[TQ_*5];

    const int qq0 = blockIdx.x * TQ_;
    const int h   = blockIdx.y;
    const int b   = blockIdx.z;
    const int tid = threadIdx.x;
    const int lrow = tid >> 1;          // 0..127
    const int lk4  = (tid & 1) * 4;

    for (int i = tid; i < 7*HD_; i += 256) { sh_relk[i] = relk[i]; sh_relv[i] = relv[i]; }
    for (int i = tid; i < TQ_*5; i += 256) sh_pmid[i] = 0.f;

    const float* qbase = gq + ((size_t)(b*L_ + qq0))*D_ + h*HD_;
    const float* kbase = gk + ((size_t)b*L_)*D_ + h*HD_;
    const float* vbase = gv + ((size_t)b*L_)*D_ + h*HD_;
    float* attn_base = attn + (((size_t)(b*H_ + h))*L_ + qq0) * L_;

    // ---- hoisted Q stage: split hi/lo into Qh/Ql[128][68] (once) ----
    {
        const int rowL = tid >> 1, khL = (tid & 1) * 8;
        #pragma unroll
        for (int t = 0; t < 4; t++) {
            int d = khL + 16*t;
            float4 q0 = *(const float4*)(qbase + (size_t)rowL*D_ + d);
            float4 q1 = *(const float4*)(qbase + (size_t)rowL*D_ + d + 4);
            float4 hh, ll;
            split4(q0, hh, ll);
            *(float4*)&Qh[rowL*68 + d] = hh; *(float4*)&Ql[rowL*68 + d] = ll;
            split4(q1, hh, ll);
            *(float4*)&Qh[rowL*68 + d + 4] = hh; *(float4*)&Ql[rowL*68 + d + 4] = ll;
        }
    }
    __syncthreads();   // relk loaded + Q staged

    // ---- rel-k bias: bias[m][r] = Q[m] . rel_k[r] ----
    for (int idx = tid; idx < TQ_*7; idx += 256) {
        int m = idx / 7, rr = idx % 7;
        float s = 0.f;
        #pragma unroll
        for (int d = 0; d < HD_; d++)
            s = fmaf(qbase[(size_t)m*D_ + d], sh_relk[rr*HD_ + d], s);
        sh_bias[idx] = s;
    }
    __syncthreads();

    // ================= pass 1: logits via split-tf32 mma =================
    const int lane = tid & 31, wid = tid >> 5;
    const int wy = wid & 3, wx = wid >> 2;
    const int gid = lane >> 2, tig = lane & 3;
    const int rowL = tid >> 1, khL = (tid & 1) * 8;

    uint32_t aQh[2], aQl[2], aKh, aKl;
    {
        int r  = 32*wy + (lane & 7) + 8*((lane >> 3) & 1);
        int kc = 4 * (lane >> 4);
        aQh[0] = smem_u32(&Qh[r*68 + kc]);
        aQh[1] = aQh[0] + 16*68*4;
        aQl[0] = smem_u32(&Ql[r*68 + kc]);
        aQl[1] = aQl[0] + 16*68*4;
        int rB  = 64*wx + (lane & 7);
        int kcB = 4 * ((lane >> 3) & 1);
        aKh = smem_u32(&Kh[rB*20 + kcB]);
        aKl = smem_u32(&Kl[rB*20 + kcB]);
    }

    float pm[2][2];
    pm[0][0] = pm[0][1] = pm[1][0] = pm[1][1] = -1e30f;

    for (int kc = 0; kc < NCH_; kc++) {
        const int k0 = kc * TK_;
        float c[2][8][4] = {};
        #pragma unroll
        for (int kt = 0; kt < 4; kt++) {
            // stage K d16-slice, split hi/lo
            {
                float4 kv0 = *(const float4*)(kbase + (size_t)(k0 + rowL)*D_ + kt*16 + khL);
                float4 kv1 = *(const float4*)(kbase + (size_t)(k0 + rowL)*D_ + kt*16 + khL + 4);
                float4 hh, ll;
                split4(kv0, hh, ll);
                *(float4*)&Kh[rowL*20 + khL] = hh; *(float4*)&Kl[rowL*20 + khL] = ll;
                split4(kv1, hh, ll);
                *(float4*)&Kh[rowL*20 + khL + 4] = hh; *(float4*)&Kl[rowL*20 + khL + 4] = ll;
            }
            __syncthreads();
            #pragma unroll
            for (int k8 = 0; k8 < 2; k8++) {
                const uint32_t koQ = (uint32_t)((kt*16 + k8*8) * 4);
                const uint32_t koK = (uint32_t)(k8 * 32);
                uint32_t ah[2][4], al[2][4];
                ldsm4(ah[0], aQh[0] + koQ);
                ldsm4(ah[1], aQh[1] + koQ);
                ldsm4(al[0], aQl[0] + koQ);
                ldsm4(al[1], aQl[1] + koQ);
                #pragma unroll
                for (int nj = 0; nj < 8; nj++) {
                    uint32_t bh[2], bl[2];
                    ldsm2(bh, aKh + (uint32_t)(nj*8*20*4) + koK);
                    ldsm2(bl, aKl + (uint32_t)(nj*8*20*4) + koK);
                    #pragma unroll
                    for (int mi = 0; mi < 2; mi++) {
                        mma8(c[mi][nj], ah[mi], bh);
                        mma8(c[mi][nj], ah[mi], bl);
                        mma8(c[mi][nj], al[mi], bh);
                    }
                }
            }
            __syncthreads();
        }
        // ---- epilogue: bias + scale + rowmax + raw-S store ----
        #pragma unroll
        for (int mi = 0; mi < 2; mi++) {
            #pragma unroll
            for (int half = 0; half < 2; half++) {
                const int m  = 32*wy + 16*mi + 8*half + gid;
                const int qg = qq0 + m;
                const float* brow = &sh_bias[m*7];
                float mx = pm[mi][half];
                #pragma unroll
                for (int nj = 0; nj < 8; nj++) {
                    const int kg = k0 + 64*wx + 8*nj + 2*tig;
                    int d0 = kg - qg, d1 = d0 + 1;
                    int r0 = d0 < -3 ? 0 : (d0 > 3 ? 6 : d0 + 3);
                    int r1 = d1 < -3 ? 0 : (d1 > 3 ? 6 : d1 + 3);
                    float s0 = 8.f * (c[mi][nj][2*half]     + brow[r0]);
                    float s1 = 8.f * (c[mi][nj][2*half + 1] + brow[r1]);
                    mx = fmaxf(mx, fmaxf(s0, s1));
                    *(float2*)&attn_base[(size_t)m*L_ + kg] = make_float2(s0, s1);
                }
                pm[mi][half] = mx;
            }
        }
    }

    // ---- rowmax reduce: tig lanes, then wx warps ----
    #pragma unroll
    for (int mi = 0; mi < 2; mi++)
        #pragma unroll
        for (int half = 0; half < 2; half++) {
            float v = pm[mi][half];
            v = fmaxf(v, __shfl_xor_sync(0xffffffffu, v, 1));
            v = fmaxf(v, __shfl_xor_sync(0xffffffffu, v, 2));
            if (tig == 0)
                sh_red[(32*wy + 16*mi + 8*half + gid)*2 + wx] = v;
        }
    __syncthreads();
    if (tid < TQ_) sh_rowmax[tid] = fmaxf(sh_red[tid*2], sh_red[tid*2 + 1]);
    __syncthreads();

    // ================= pass 2: exp + sums + PV via mma ====================
    const int m2   = lrow;
    const int c0   = lk4;
    const int qg2  = qq0 + m2;
    const float rm2 = sh_rowmax[m2];

    // PV warp layout: 4 wy (m: 32 rows) x 2 wx (d: 32 cols)
    uint32_t aE[2];
    {
        int r  = 32*wy + (lane & 7) + 8*((lane >> 3) & 1);
        int kcc = 4 * (lane >> 4);
        aE[0] = smem_u32(&Es[r*132 + kcc]);
        aE[1] = aE[0] + 16*132*4;
    }
    const int dbase = 32*wx;
    const int kvrow = tid >> 2, dv0 = (tid & 3) * 16;

    float tsum = 0.f, s0sum = 0.f, s6sum = 0.f;
    float c2[2][4][4] = {};

    for (int kc = 0; kc < NCH_; kc++) {
        const int k0 = kc * TK_;
        // ---- stage V half0 (k0..k0+63), tf32-rounded ----
        #pragma unroll
        for (int t = 0; t < 4; t++) {
            float4 v = *(const float4*)(vbase + (size_t)(k0 + kvrow)*D_ + dv0 + 4*t);
            v.x = tf32_rna(v.x); v.y = tf32_rna(v.y);
            v.z = tf32_rna(v.z); v.w = tf32_rna(v.w);
            *(float4*)&Vs[kvrow*68 + dv0 + 4*t] = v;
        }
        // ---- exp stage: sums + write-back e~ (fp32) + tf32 E to smem ----
        #pragma unroll
        for (int r = 0; r < 16; r++) {
            int c = c0 + 8*r;
            float* gp = attn_base + (size_t)m2*L_ + k0 + c;
            float4 sv = *(const float4*)gp;
            float e0 = __expf(sv.x - rm2);
            float e1 = __expf(sv.y - rm2);
            float e2 = __expf(sv.z - rm2);
            float e3 = __expf(sv.w - rm2);
            tsum += e0 + e1 + e2 + e3;
            #pragma unroll
            for (int j = 0; j < 4; j++) {
                float e = (j == 0) ? e0 : (j == 1) ? e1 : (j == 2) ? e2 : e3;
                int dlt = k0 + c + j - qg2;
                if (dlt <= -3)      s0sum += e;
                else if (dlt >= 3)  s6sum += e;
                else                sh_pmid[m2*5 + dlt + 2] = e;
            }
            *(float4*)gp = make_float4(e0, e1, e2, e3);   // e~ back to attn
            float4 er = make_float4(tf32_rna(e0), tf32_rna(e1), tf32_rna(e2), tf32_rna(e3));
            *(float4*)&Es[m2*132 + c] = er;
        }
        __syncthreads();

        // ---- PV mma half0 ----
        #pragma unroll
        for (int k8 = 0; k8 < 8; k8++) {
            const uint32_t ko = (uint32_t)(k8 * 32);
            uint32_t a[2][4];
            ldsm4(a[0], aE[0] + ko);
            ldsm4(a[1], aE[1] + ko);
            #pragma unroll
            for (int nj = 0; nj < 4; nj++) {
                uint32_t bb[2];
                bb[0] = __float_as_uint(Vs[(k8*8 + tig    )*68 + dbase + 8*nj + gid]);
                bb[1] = __float_as_uint(Vs[(k8*8 + tig + 4)*68 + dbase + 8*nj + gid]);
                mma8(c2[0][nj], a[0], bb);
                mma8(c2[1][nj], a[1], bb);
            }
        }
        __syncthreads();
        // ---- stage V half1 ----
        #pragma unroll
        for (int t = 0; t < 4; t++) {
            float4 v = *(const float4*)(vbase + (size_t)(k0 + 64 + kvrow)*D_ + dv0 + 4*t);
            v.x = tf32_rna(v.x); v.y = tf32_rna(v.y);
            v.z = tf32_rna(v.z); v.w = tf32_rna(v.w);
            *(float4*)&Vs[kvrow*68 + dv0 + 4*t] = v;
        }
        __syncthreads();
        // ---- PV mma half1 ----
        #pragma unroll
        for (int k8 = 0; k8 < 8; k8++) {
            const uint32_t ko = (uint32_t)((64 + k8*8) * 4);
            uint32_t a[2][4];
            ldsm4(a[0], aE[0] + ko);
            ldsm4(a[1], aE[1] + ko);
            #pragma unroll
            for (int nj = 0; nj < 4; nj++) {
                uint32_t bb[2];
                bb[0] = __float_as_uint(Vs[(k8*8 + tig    )*68 + dbase + 8*nj + gid]);
                bb[1] = __float_as_uint(Vs[(k8*8 + tig + 4)*68 + dbase + 8*nj + gid]);
                mma8(c2[0][nj], a[0], bb);
                mma8(c2[1][nj], a[1], bb);
            }
        }
        __syncthreads();
    }

    // ---- row-sum pair reduce (two threads per row) ----
    tsum  += __shfl_xor_sync(0xffffffffu, tsum,  1);
    s0sum += __shfl_xor_sync(0xffffffffu, s0sum, 1);
    s6sum += __shfl_xor_sync(0xffffffffu, s6sum, 1);
    if ((tid & 1) == 0) { sh_T[m2] = tsum; sh_S0[m2] = s0sum; sh_S6[m2] = s6sum; }
    __syncthreads();

    // ---- w = (PV + w2) * invT from fragments -> gw [B,L,H,hd] ----
    {
        float* wbase = gw + ((size_t)(b*L_ + qq0))*D_ + h*HD_;
        #pragma unroll
        for (int mi = 0; mi < 2; mi++) {
            #pragma unroll
            for (int half = 0; half < 2; half++) {
                const int m = 32*wy + 16*mi + 8*half + gid;
                float T  = sh_T[m];
                float S0 = sh_S0[m];
                float S6 = sh_S6[m];
                float inv = 1.f / T;
                float mids[5];
                #pragma unroll
                for (int rr = 0; rr < 5; rr++) mids[rr] = sh_pmid[m*5 + rr];
                #pragma unroll
                for (int nj = 0; nj < 4; nj++) {
                    const int d0c = 32*wx + 8*nj + 2*tig;
                    float w2a = S0 * sh_relv[d0c]     + S6 * sh_relv[6*HD_ + d0c];
                    float w2b = S0 * sh_relv[d0c + 1] + S6 * sh_relv[6*HD_ + d0c + 1];
                    #pragma unroll
                    for (int rr = 0; rr < 5; rr++) {
                        w2a = fmaf(mids[rr], sh_relv[(rr+1)*HD_ + d0c],     w2a);
                        w2b = fmaf(mids[rr], sh_relv[(rr+1)*HD_ + d0c + 1], w2b);
                    }
                    float2 o;
                    o.x = (c2[mi][nj][2*half]     + w2a) * inv;
                    o.y = (c2[mi][nj][2*half + 1] + w2b) * inv;
                    *(float2*)(wbase + (size_t)m*D_ + d0c) = o;
                }
            }
        }
    }

    // ================= pass 3: scale e~ by 1/T (no exp) =================
    const float inv3 = 1.f / sh_T[m2];
    #pragma unroll 4
    for (int r = 0; r < 128; r++) {
        int c = c0 + 8*r;
        float* p = attn_base + (size_t)m2*L_ + c;
        float4 a = *(const float4*)p;
        a.x *= inv3; a.y *= inv3; a.z *= inv3; a.w *= inv3;
        *(float4*)p = a;
    }
}

// ---------------- launch ----------------
extern "C" void kernel_launch(void* const* d_in, const int* in_sizes, int n_in,
                              void* d_out, int out_size)
{
    const float* query  = (const float*)d_in[0];
    const float* key    = (const float*)d_in[1];
    const float* value  = (const float*)d_in[2];
    const float* Wq     = (const float*)d_in[3];
    const float* Wk     = (const float*)d_in[4];
    const float* Wv     = (const float*)d_in[5];
    const float* Wproj  = (const float*)d_in[6];
    const float* b_proj = (const float*)d_in[7];
    const float* relk   = (const float*)d_in[8];
    const float* relv   = (const float*)d_in[9];

    float* out  = (float*)d_out;
    float* attn = out + (size_t)B_ * L_ * D_;   // x first, then attn

    float *gq, *gk, *gv, *gw;
    cudaGetSymbolAddress((void**)&gq, g_q);
    cudaGetSymbolAddress((void**)&gk, g_k);
    cudaGetSymbolAddress((void**)&gv, g_v);
    cudaGetSymbolAddress((void**)&gw, g_w);

    cudaFuncSetAttribute(attn_kernel, cudaFuncAttributeMaxDynamicSharedMemorySize,
                         DYN_SMEM_BYTES);
    cudaFuncSetAttribute(mma_qkv_kernel, cudaFuncAttributeMaxDynamicSharedMemorySize,
                         GEMM_SMEM);
    cudaFuncSetAttribute(mma_proj_kernel, cudaFuncAttributeMaxDynamicSharedMemorySize,
                         GEMM_SMEM);

    mma_qkv_kernel<<<dim3(18, 32), 256, GEMM_SMEM>>>(query, key, value,
                                                     Wq, Wk, Wv, gq, gk, gv);

    attn_kernel<<<dim3(L_/TQ_, H_, B_), 256, DYN_SMEM_BYTES>>>(
        gq, gk, gv, relk, relv, attn, gw);

    mma_proj_kernel<<<dim3(6, 32), 256, GEMM_SMEM>>>(gw, Wproj, b_proj, out);
}

// round 16
// speedup vs baseline: 2.0430x; 2.0430x over previous
#include <cuda_runtime.h>
#include <math.h>
#include <stdint.h>

typedef unsigned long long u64;

static constexpr int B_  = 4;
static constexpr int L_  = 1024;
static constexpr int D_  = 768;
static constexpr int H_  = 12;
static constexpr int HD_ = 64;
static constexpr int TQ_ = 128;
static constexpr int TK_ = 128;
static constexpr int NCH_ = L_ / TK_;   // 8

// attn dynamic smem: pass1 Qh/Ql[128][68] + Kh/Kl[128][20] = 22528 floats
static constexpr int DYN_SMEM_BYTES = (2*128*68 + 2*128*20) * 4;   // 90112

// mma GEMM config
static constexpr int KT  = 16;          // k-tile
static constexpr int NKT = D_ / KT;     // 48
static constexpr int PAD = 20;          // floats per smem row (16 used)
static constexpr int STAGE_F = 128*PAD;             // floats per tile-stage
static constexpr int GEMM_SMEM = 8 * STAGE_F * 4;   // 2 stages x 4 arrays = 81920B

// ---------------- mma.sync helpers ----------------
__device__ __forceinline__ uint32_t smem_u32(const void* p) {
    uint32_t a;
    asm("{ .reg .u64 t; cvta.to.shared.u64 t, %1; cvt.u32.u64 %0, t; }"
        : "=r"(a) : "l"(p));
    return a;
}
__device__ __forceinline__ float tf32_rna(float x) {
    uint32_t r; asm("cvt.rna.tf32.f32 %0, %1;" : "=r"(r) : "f"(x));
    return __uint_as_float(r);
}
__device__ __forceinline__ void ldsm4(uint32_t r[4], uint32_t a) {
    asm volatile("ldmatrix.sync.aligned.m8n8.x4.shared.b16 {%0,%1,%2,%3}, [%4];"
        : "=r"(r[0]), "=r"(r[1]), "=r"(r[2]), "=r"(r[3]) : "r"(a));
}
__device__ __forceinline__ void ldsm2(uint32_t r[2], uint32_t a) {
    asm volatile("ldmatrix.sync.aligned.m8n8.x2.shared.b16 {%0,%1}, [%2];"
        : "=r"(r[0]), "=r"(r[1]) : "r"(a));
}
__device__ __forceinline__ void mma8(float c[4], const uint32_t a[4],
                                     const uint32_t b[2]) {
    asm volatile(
        "mma.sync.aligned.m16n8k8.row.col.f32.tf32.tf32.f32 "
        "{%0,%1,%2,%3}, {%4,%5,%6,%7}, {%8,%9}, {%0,%1,%2,%3};"
        : "+f"(c[0]), "+f"(c[1]), "+f"(c[2]), "+f"(c[3])
        : "r"(a[0]), "r"(a[1]), "r"(a[2]), "r"(a[3]), "r"(b[0]), "r"(b[1]));
}
// split a float4 into tf32 hi / fp32 residual lo
__device__ __forceinline__ void split4(float4 v, float4& h, float4& l) {
    h.x = tf32_rna(v.x); l.x = v.x - h.x;
    h.y = tf32_rna(v.y); l.y = v.y - h.y;
    h.z = tf32_rna(v.z); l.z = v.z - h.z;
    h.w = tf32_rna(v.w); l.w = v.w - h.w;
}

// ---------------- device scratch ----------------
__device__ float g_q[(size_t)B_ * L_ * D_];
__device__ float g_k[(size_t)B_ * L_ * D_];
__device__ float g_v[(size_t)B_ * L_ * D_];
__device__ float g_w[(size_t)B_ * L_ * D_];

// ---------------- split-tf32 mma GEMM, double-buffered (R15, verified) ----
// 8 warps: 4 wy (m) x 2 wx (n); warp tile 32m x 64n. One barrier per k-tile.
__device__ __forceinline__ void mma_gemm_tile128(const float* __restrict__ A,
                                                 const float* __restrict__ W,
                                                 const float* __restrict__ bias,
                                                 float* __restrict__ C,
                                                 int m0, int n0)
{
    extern __shared__ float gsm[];
    float* Ah = gsm;                    // [2][128*PAD]
    float* Al = gsm + 2*STAGE_F;
    float* Bh = gsm + 4*STAGE_F;
    float* Bl = gsm + 6*STAGE_F;

    const int tid  = threadIdx.x;
    const int lane = tid & 31, wid = tid >> 5;
    const int wy = wid & 3, wx = wid >> 2;
    const int gid = lane >> 2, tig = lane & 3;

    const int rowL = tid >> 1, khL = (tid & 1) * 8;
    const float* Ap = A + (size_t)(m0 + rowL) * D_ + khL;
    const float* Wp = W + (size_t)(n0 + rowL) * D_ + khL;

    uint32_t aAh[2], aAl[2], aBh, aBl;
    {
        int r  = 32*wy + (lane & 7) + 8*((lane >> 3) & 1);
        int kc = 4 * (lane >> 4);
        aAh[0] = smem_u32(&Ah[r*PAD + kc]);
        aAh[1] = aAh[0] + 16*PAD*4;
        aAl[0] = smem_u32(&Al[r*PAD + kc]);
        aAl[1] = aAl[0] + 16*PAD*4;
        int rB  = 64*wx + (lane & 7);
        int kcB = 4 * ((lane >> 3) & 1);
        aBh = smem_u32(&Bh[rB*PAD + kcB]);
        aBl = smem_u32(&Bl[rB*PAD + kcB]);
    }

    float c[2][8][4] = {};

    // prologue: load + stage kt=0 into stage 0
    float4 va0 = *(const float4*)(Ap);
    float4 va1 = *(const float4*)(Ap + 4);
    float4 vb0 = *(const float4*)(Wp);
    float4 vb1 = *(const float4*)(Wp + 4);
    {
        float4 h, l;
        split4(va0, h, l);
        *(float4*)&Ah[rowL*PAD + khL] = h; *(float4*)&Al[rowL*PAD + khL] = l;
        split4(va1, h, l);
        *(float4*)&Ah[rowL*PAD + khL + 4] = h; *(float4*)&Al[rowL*PAD + khL + 4] = l;
        split4(vb0, h, l);
        *(float4*)&Bh[rowL*PAD + khL] = h; *(float4*)&Bl[rowL*PAD + khL] = l;
        split4(vb1, h, l);
        *(float4*)&Bh[rowL*PAD + khL + 4] = h; *(float4*)&Bl[rowL*PAD + khL + 4] = l;
    }
    __syncthreads();

    for (int kt = 0; kt < NKT; kt++) {
        if (kt + 1 < NKT) {
            va0 = *(const float4*)(Ap + (kt+1)*KT);
            va1 = *(const float4*)(Ap + (kt+1)*KT + 4);
            vb0 = *(const float4*)(Wp + (kt+1)*KT);
            vb1 = *(const float4*)(Wp + (kt+1)*KT + 4);
        }
        const uint32_t sboff = (uint32_t)((kt & 1) * STAGE_F * 4);
        #pragma unroll
        for (int k8 = 0; k8 < 2; k8++) {
            const uint32_t ko = sboff + (uint32_t)(k8 * 32);
            uint32_t ah[2][4], al[2][4];
            ldsm4(ah[0], aAh[0] + ko);
            ldsm4(ah[1], aAh[1] + ko);
            ldsm4(al[0], aAl[0] + ko);
            ldsm4(al[1], aAl[1] + ko);
            #pragma unroll
            for (int nj = 0; nj < 8; nj++) {
                uint32_t bh[2], bl[2];
                ldsm2(bh, aBh + (uint32_t)(nj*8*PAD*4) + ko);
                ldsm2(bl, aBl + (uint32_t)(nj*8*PAD*4) + ko);
                #pragma unroll
                for (int mi = 0; mi < 2; mi++) {
                    mma8(c[mi][nj], ah[mi], bh);
                    mma8(c[mi][nj], ah[mi], bl);
                    mma8(c[mi][nj], al[mi], bh);
                }
            }
        }
        if (kt + 1 < NKT) {
            const int st = ((kt + 1) & 1) * STAGE_F;
            float4 h, l;
            split4(va0, h, l);
            *(float4*)&Ah[st + rowL*PAD + khL] = h; *(float4*)&Al[st + rowL*PAD + khL] = l;
            split4(va1, h, l);
            *(float4*)&Ah[st + rowL*PAD + khL + 4] = h; *(float4*)&Al[st + rowL*PAD + khL + 4] = l;
            split4(vb0, h, l);
            *(float4*)&Bh[st + rowL*PAD + khL] = h; *(float4*)&Bl[st + rowL*PAD + khL] = l;
            split4(vb1, h, l);
            *(float4*)&Bh[st + rowL*PAD + khL + 4] = h; *(float4*)&Bl[st + rowL*PAD + khL + 4] = l;
        }
        __syncthreads();
    }

    #pragma unroll
    for (int mi = 0; mi < 2; mi++) {
        const int r0 = m0 + 32*wy + 16*mi + gid;
        #pragma unroll
        for (int nj = 0; nj < 8; nj++) {
            const int cc = n0 + 64*wx + 8*nj + 2*tig;
            float2 v0 = make_float2(c[mi][nj][0], c[mi][nj][1]);
            float2 v1 = make_float2(c[mi][nj][2], c[mi][nj][3]);
            if (bias) {
                float bx = bias[cc], by = bias[cc+1];
                v0.x += bx; v0.y += by;
                v1.x += bx; v1.y += by;
            }
            *(float2*)&C[(size_t)r0 * D_ + cc]       = v0;
            *(float2*)&C[(size_t)(r0 + 8) * D_ + cc] = v1;
        }
    }
}

__global__ __launch_bounds__(256)
void mma_qkv_kernel(const float* __restrict__ Aq, const float* __restrict__ Ak,
                    const float* __restrict__ Av,
                    const float* __restrict__ Wq, const float* __restrict__ Wk,
                    const float* __restrict__ Wv,
                    float* __restrict__ Cq, float* __restrict__ Ck,
                    float* __restrict__ Cv)
{
    const int sel = blockIdx.x / 6;
    const int n0  = (blockIdx.x % 6) * 128;
    const int m0  = blockIdx.y * 128;
    const float* A = (sel == 0) ? Aq : (sel == 1) ? Ak : Av;
    const float* W = (sel == 0) ? Wq : (sel == 1) ? Wk : Wv;
    float*       C = (sel == 0) ? Cq : (sel == 1) ? Ck : Cv;
    mma_gemm_tile128(A, W, nullptr, C, m0, n0);
}

__global__ __launch_bounds__(256)
void mma_proj_kernel(const float* __restrict__ A, const float* __restrict__ W,
                     const float* __restrict__ bias, float* __restrict__ C)
{
    mma_gemm_tile128(A, W, bias, C, blockIdx.y * 128, blockIdx.x * 128);
}

// ---------------- attention: all-mma (R14 champion, verbatim) ------------
__global__ __launch_bounds__(256, 2)
void attn_kernel(const float* __restrict__ gq, const float* __restrict__ gk,
                 const float* __restrict__ gv,
                 const float* __restrict__ relk, const float* __restrict__ relv,
                 float* __restrict__ attn, float* __restrict__ gw)
{
    extern __shared__ float dsm[];
    // pass1 views
    float* Qh = dsm;                        // [128][68]
    float* Ql = dsm + 128*68;               // [128][68]
    float* Kh = dsm + 2*128*68;             // [128][20]
    float* Kl = dsm + 2*128*68 + 128*20;    // [128][20]
    // pass2 views (overlap)
    float* Es = dsm;                        // [128 m][132 k] row-major tf32
    float* Vs = dsm + 128*132;              // [64 k][68 d]  tf32 (half-chunk)

    __shared__ float sh_relk[7*HD_];
    __shared__ float sh_relv[7*HD_];
    __shared__ float sh_bias[TQ_*7];
    __shared__ float sh_rowmax[TQ_];
    __shared__ float sh_red[TQ_*2];
    __shared__ float sh_T[TQ_];
    __shared__ float sh_S0[TQ_];
    __shared__ float sh_S6[TQ_];
    __shared__ float sh_pmid[TQ_*5];

    const int qq0 = blockIdx.x * TQ_;
    const int h   = blockIdx.y;
    const int b   = blockIdx.z;
    const int tid = threadIdx.x;
    const int lrow = tid >> 1;          // 0..127
    const int lk4  = (tid & 1) * 4;

    for (int i = tid; i < 7*HD_; i += 256) { sh_relk[i] = relk[i]; sh_relv[i] = relv[i]; }
    for (int i = tid; i < TQ_*5; i += 256) sh_pmid[i] = 0.f;

    const float* qbase = gq + ((size_t)(b*L_ + qq0))*D_ + h*HD_;
    const float* kbase = gk + ((size_t)b*L_)*D_ + h*HD_;
    const float* vbase = gv + ((size_t)b*L_)*D_ + h*HD_;
    float* attn_base = attn + (((size_t)(b*H_ + h))*L_ + qq0) * L_;

    // ---- hoisted Q stage: split hi/lo into Qh/Ql[128][68] (once) ----
    {
        const int rowL = tid >> 1, khL = (tid & 1) * 8;
        #pragma unroll
        for (int t = 0; t < 4; t++) {
            int d = khL + 16*t;
            float4 q0 = *(const float4*)(qbase + (size_t)rowL*D_ + d);
            float4 q1 = *(const float4*)(qbase + (size_t)rowL*D_ + d + 4);
            float4 hh, ll;
            split4(q0, hh, ll);
            *(float4*)&Qh[rowL*68 + d] = hh; *(float4*)&Ql[rowL*68 + d] = ll;
            split4(q1, hh, ll);
            *(float4*)&Qh[rowL*68 + d + 4] = hh; *(float4*)&Ql[rowL*68 + d + 4] = ll;
        }
    }
    __syncthreads();   // relk loaded + Q staged

    // ---- rel-k bias: bias[m][r] = Q[m] . rel_k[r] ----
    for (int idx = tid; idx < TQ_*7; idx += 256) {
        int m = idx / 7, rr = idx % 7;
        float s = 0.f;
        #pragma unroll
        for (int d = 0; d < HD_; d++)
            s = fmaf(qbase[(size_t)m*D_ + d], sh_relk[rr*HD_ + d], s);
        sh_bias[idx] = s;
    }
    __syncthreads();

    // ================= pass 1: logits via split-tf32 mma =================
    const int lane = tid & 31, wid = tid >> 5;
    const int wy = wid & 3, wx = wid >> 2;
    const int gid = lane >> 2, tig = lane & 3;
    const int rowL = tid >> 1, khL = (tid & 1) * 8;

    uint32_t aQh[2], aQl[2], aKh, aKl;
    {
        int r  = 32*wy + (lane & 7) + 8*((lane >> 3) & 1);
        int kc = 4 * (lane >> 4);
        aQh[0] = smem_u32(&Qh[r*68 + kc]);
        aQh[1] = aQh[0] + 16*68*4;
        aQl[0] = smem_u32(&Ql[r*68 + kc]);
        aQl[1] = aQl[0] + 16*68*4;
        int rB  = 64*wx + (lane & 7);
        int kcB = 4 * ((lane >> 3) & 1);
        aKh = smem_u32(&Kh[rB*20 + kcB]);
        aKl = smem_u32(&Kl[rB*20 + kcB]);
    }

    float pm[2][2];
    pm[0][0] = pm[0][1] = pm[1][0] = pm[1][1] = -1e30f;

    for (int kc = 0; kc < NCH_; kc++) {
        const int k0 = kc * TK_;
        float c[2][8][4] = {};
        #pragma unroll
        for (int kt = 0; kt < 4; kt++) {
            // stage K d16-slice, split hi/lo
            {
                float4 kv0 = *(const float4*)(kbase + (size_t)(k0 + rowL)*D_ + kt*16 + khL);
                float4 kv1 = *(const float4*)(kbase + (size_t)(k0 + rowL)*D_ + kt*16 + khL + 4);
                float4 hh, ll;
                split4(kv0, hh, ll);
                *(float4*)&Kh[rowL*20 + khL] = hh; *(float4*)&Kl[rowL*20 + khL] = ll;
                split4(kv1, hh, ll);
                *(float4*)&Kh[rowL*20 + khL + 4] = hh; *(float4*)&Kl[rowL*20 + khL + 4] = ll;
            }
            __syncthreads();
            #pragma unroll
            for (int k8 = 0; k8 < 2; k8++) {
                const uint32_t koQ = (uint32_t)((kt*16 + k8*8) * 4);
                const uint32_t koK = (uint32_t)(k8 * 32);
                uint32_t ah[2][4], al[2][4];
                ldsm4(ah[0], aQh[0] + koQ);
                ldsm4(ah[1], aQh[1] + koQ);
                ldsm4(al[0], aQl[0] + koQ);
                ldsm4(al[1], aQl[1] + koQ);
                #pragma unroll
                for (int nj = 0; nj < 8; nj++) {
                    uint32_t bh[2], bl[2];
                    ldsm2(bh, aKh + (uint32_t)(nj*8*20*4) + koK);
                    ldsm2(bl, aKl + (uint32_t)(nj*8*20*4) + koK);
                    #pragma unroll
                    for (int mi = 0; mi < 2; mi++) {
                        mma8(c[mi][nj], ah[mi], bh);
                        mma8(c[mi][nj], ah[mi], bl);
                        mma8(c[mi][nj], al[mi], bh);
                    }
                }
            }
            __syncthreads();
        }
        // ---- epilogue: bias + scale + rowmax + raw-S store ----
        #pragma unroll
        for (int mi = 0; mi < 2; mi++) {
            #pragma unroll
            for (int half = 0; half < 2; half++) {
                const int m  = 32*wy + 16*mi + 8*half + gid;
                const int qg = qq0 + m;
                const float* brow = &sh_bias[m*7];
                float mx = pm[mi][half];
                #pragma unroll
                for (int nj = 0; nj < 8; nj++) {
                    const int kg = k0 + 64*wx + 8*nj + 2*tig;
                    int d0 = kg - qg, d1 = d0 + 1;
                    int r0 = d0 < -3 ? 0 : (d0 > 3 ? 6 : d0 + 3);
                    int r1 = d1 < -3 ? 0 : (d1 > 3 ? 6 : d1 + 3);
                    float s0 = 8.f * (c[mi][nj][2*half]     + brow[r0]);
                    float s1 = 8.f * (c[mi][nj][2*half + 1] + brow[r1]);
                    mx = fmaxf(mx, fmaxf(s0, s1));
                    *(float2*)&attn_base[(size_t)m*L_ + kg] = make_float2(s0, s1);
                }
                pm[mi][half] = mx;
            }
        }
    }

    // ---- rowmax reduce: tig lanes, then wx warps ----
    #pragma unroll
    for (int mi = 0; mi < 2; mi++)
        #pragma unroll
        for (int half = 0; half < 2; half++) {
            float v = pm[mi][half];
            v = fmaxf(v, __shfl_xor_sync(0xffffffffu, v, 1));
            v = fmaxf(v, __shfl_xor_sync(0xffffffffu, v, 2));
            if (tig == 0)
                sh_red[(32*wy + 16*mi + 8*half + gid)*2 + wx] = v;
        }
    __syncthreads();
    if (tid < TQ_) sh_rowmax[tid] = fmaxf(sh_red[tid*2], sh_red[tid*2 + 1]);
    __syncthreads();

    // ================= pass 2: exp + sums + PV via mma ====================
    const int m2   = lrow;
    const int c0   = lk4;
    const int qg2  = qq0 + m2;
    const float rm2 = sh_rowmax[m2];

    // PV warp layout: 4 wy (m: 32 rows) x 2 wx (d: 32 cols)
    uint32_t aE[2];
    {
        int r  = 32*wy + (lane & 7) + 8*((lane >> 3) & 1);
        int kcc = 4 * (lane >> 4);
        aE[0] = smem_u32(&Es[r*132 + kcc]);
        aE[1] = aE[0] + 16*132*4;
    }
    const int dbase = 32*wx;      // warp's d block (within 64)
    const int kvrow = tid >> 2, dv0 = (tid & 3) * 16;   // V loader indices

    float tsum = 0.f, s0sum = 0.f, s6sum = 0.f;
    float c2[2][4][4] = {};       // [mi][nj d8][frag]

    for (int kc = 0; kc < NCH_; kc++) {
        const int k0 = kc * TK_;
        // ---- stage V half0 (k0..k0+63), tf32-rounded ----
        #pragma unroll
        for (int t = 0; t < 4; t++) {
            float4 v = *(const float4*)(vbase + (size_t)(k0 + kvrow)*D_ + dv0 + 4*t);
            v.x = tf32_rna(v.x); v.y = tf32_rna(v.y);
            v.z = tf32_rna(v.z); v.w = tf32_rna(v.w);
            *(float4*)&Vs[kvrow*68 + dv0 + 4*t] = v;
        }
        // ---- exp stage: full-precision sums, tf32-rounded E to smem ----
        #pragma unroll
        for (int r = 0; r < 16; r++) {
            int c = c0 + 8*r;
            float4 sv = *(const float4*)(attn_base + (size_t)m2*L_ + k0 + c);
            float e0 = __expf(sv.x - rm2);
            float e1 = __expf(sv.y - rm2);
            float e2 = __expf(sv.z - rm2);
            float e3 = __expf(sv.w - rm2);
            tsum += e0 + e1 + e2 + e3;
            #pragma unroll
            for (int j = 0; j < 4; j++) {
                float e = (j == 0) ? e0 : (j == 1) ? e1 : (j == 2) ? e2 : e3;
                int dlt = k0 + c + j - qg2;
                if (dlt <= -3)      s0sum += e;
                else if (dlt >= 3)  s6sum += e;
                else                sh_pmid[m2*5 + dlt + 2] = e;
            }
            float4 er = make_float4(tf32_rna(e0), tf32_rna(e1), tf32_rna(e2), tf32_rna(e3));
            *(float4*)&Es[m2*132 + c] = er;
        }
        __syncthreads();

        // ---- PV mma half0 (k8 = 0..7) ----
        #pragma unroll
        for (int k8 = 0; k8 < 8; k8++) {
            const uint32_t ko = (uint32_t)(k8 * 32);
            uint32_t a[2][4];
            ldsm4(a[0], aE[0] + ko);
            ldsm4(a[1], aE[1] + ko);
            #pragma unroll
            for (int nj = 0; nj < 4; nj++) {
                uint32_t bb[2];
                bb[0] = __float_as_uint(Vs[(k8*8 + tig    )*68 + dbase + 8*nj + gid]);
                bb[1] = __float_as_uint(Vs[(k8*8 + tig + 4)*68 + dbase + 8*nj + gid]);
                mma8(c2[0][nj], a[0], bb);
                mma8(c2[1][nj], a[1], bb);
            }
        }
        __syncthreads();
        // ---- stage V half1 (k0+64..k0+127) ----
        #pragma unroll
        for (int t = 0; t < 4; t++) {
            float4 v = *(const float4*)(vbase + (size_t)(k0 + 64 + kvrow)*D_ + dv0 + 4*t);
            v.x = tf32_rna(v.x); v.y = tf32_rna(v.y);
            v.z = tf32_rna(v.z); v.w = tf32_rna(v.w);
            *(float4*)&Vs[kvrow*68 + dv0 + 4*t] = v;
        }
        __syncthreads();
        // ---- PV mma half1 (k8 = 8..15 of Es, rows 0..63 of Vs) ----
        #pragma unroll
        for (int k8 = 0; k8 < 8; k8++) {
            const uint32_t ko = (uint32_t)((64 + k8*8) * 4);
            uint32_t a[2][4];
            ldsm4(a[0], aE[0] + ko);
            ldsm4(a[1], aE[1] + ko);
            #pragma unroll
            for (int nj = 0; nj < 4; nj++) {
                uint32_t bb[2];
                bb[0] = __float_as_uint(Vs[(k8*8 + tig    )*68 + dbase + 8*nj + gid]);
                bb[1] = __float_as_uint(Vs[(k8*8 + tig + 4)*68 + dbase + 8*nj + gid]);
                mma8(c2[0][nj], a[0], bb);
                mma8(c2[1][nj], a[1], bb);
            }
        }
        __syncthreads();
    }

    // ---- row-sum pair reduce (two threads per row) ----
    tsum  += __shfl_xor_sync(0xffffffffu, tsum,  1);
    s0sum += __shfl_xor_sync(0xffffffffu, s0sum, 1);
    s6sum += __shfl_xor_sync(0xffffffffu, s6sum, 1);
    if ((tid & 1) == 0) { sh_T[m2] = tsum; sh_S0[m2] = s0sum; sh_S6[m2] = s6sum; }
    __syncthreads();

    // ---- w = (PV + w2) * invT from fragments -> gw [B,L,H,hd] ----
    {
        float* wbase = gw + ((size_t)(b*L_ + qq0))*D_ + h*HD_;
        #pragma unroll
        for (int mi = 0; mi < 2; mi++) {
            #pragma unroll
            for (int half = 0; half < 2; half++) {
                const int m = 32*wy + 16*mi + 8*half + gid;
                float T  = sh_T[m];
                float S0 = sh_S0[m];
                float S6 = sh_S6[m];
                float inv = 1.f / T;
                float mids[5];
                #pragma unroll
                for (int rr = 0; rr < 5; rr++) mids[rr] = sh_pmid[m*5 + rr];
                #pragma unroll
                for (int nj = 0; nj < 4; nj++) {
                    const int d0c = 32*wx + 8*nj + 2*tig;
                    float w2a = S0 * sh_relv[d0c]     + S6 * sh_relv[6*HD_ + d0c];
                    float w2b = S0 * sh_relv[d0c + 1] + S6 * sh_relv[6*HD_ + d0c + 1];
                    #pragma unroll
                    for (int rr = 0; rr < 5; rr++) {
                        w2a = fmaf(mids[rr], sh_relv[(rr+1)*HD_ + d0c],     w2a);
                        w2b = fmaf(mids[rr], sh_relv[(rr+1)*HD_ + d0c + 1], w2b);
                    }
                    float2 o;
                    o.x = (c2[mi][nj][2*half]     + w2a) * inv;
                    o.y = (c2[mi][nj][2*half + 1] + w2b) * inv;
                    *(float2*)(wbase + (size_t)m*D_ + d0c) = o;
                }
            }
        }
    }

    // ================= pass 3: normalized attn out =================
    const float inv3 = 1.f / sh_T[m2];
    #pragma unroll 4
    for (int r = 0; r < 128; r++) {
        int c = c0 + 8*r;
        float* p = attn_base + (size_t)m2*L_ + c;
        float4 a = *(const float4*)p;
        a.x = __expf(a.x - rm2) * inv3;
        a.y = __expf(a.y - rm2) * inv3;
        a.z = __expf(a.z - rm2) * inv3;
        a.w = __expf(a.w - rm2) * inv3;
        *(float4*)p = a;
    }
}

// ---------------- launch ----------------
extern "C" void kernel_launch(void* const* d_in, const int* in_sizes, int n_in,
                              void* d_out, int out_size)
{
    const float* query  = (const float*)d_in[0];
    const float* key    = (const float*)d_in[1];
    const float* value  = (const float*)d_in[2];
    const float* Wq     = (const float*)d_in[3];
    const float* Wk     = (const float*)d_in[4];
    const float* Wv     = (const float*)d_in[5];
    const float* Wproj  = (const float*)d_in[6];
    const float* b_proj = (const float*)d_in[7];
    const float* relk   = (const float*)d_in[8];
    const float* relv   = (const float*)d_in[9];

    float* out  = (float*)d_out;
    float* attn = out + (size_t)B_ * L_ * D_;   // x first, then attn

    float *gq, *gk, *gv, *gw;
    cudaGetSymbolAddress((void**)&gq, g_q);
    cudaGetSymbolAddress((void**)&gk, g_k);
    cudaGetSymbolAddress((void**)&gv, g_v);
    cudaGetSymbolAddress((void**)&gw, g_w);

    cudaFuncSetAttribute(attn_kernel, cudaFuncAttributeMaxDynamicSharedMemorySize,
                         DYN_SMEM_BYTES);
    cudaFuncSetAttribute(mma_qkv_kernel, cudaFuncAttributeMaxDynamicSharedMemorySize,
                         GEMM_SMEM);
    cudaFuncSetAttribute(mma_proj_kernel, cudaFuncAttributeMaxDynamicSharedMemorySize,
                         GEMM_SMEM);

    mma_qkv_kernel<<<dim3(18, 32), 256, GEMM_SMEM>>>(query, key, value,
                                                     Wq, Wk, Wv, gq, gk, gv);

    attn_kernel<<<dim3(L_/TQ_, H_, B_), 256, DYN_SMEM_BYTES>>>(
        gq, gk, gv, relk, relv, attn, gw);

    mma_proj_kernel<<<dim3(6, 32), 256, GEMM_SMEM>>>(gw, Wproj, b_proj, out);
}

// round 17
// speedup vs baseline: 2.2806x; 1.1163x over previous
#include <cuda_runtime.h>
#include <math.h>
#include <stdint.h>

typedef unsigned long long u64;

static constexpr int B_  = 4;
static constexpr int L_  = 1024;
static constexpr int D_  = 768;
static constexpr int H_  = 12;
static constexpr int HD_ = 64;
static constexpr int TQ_ = 128;
static constexpr int TK_ = 128;
static constexpr int NCH_ = L_ / TK_;   // 8

// attn dynamic smem: pass1 Qh/Ql[128][68] + Kh/Kl[128][20] = 22528 floats
static constexpr int DYN_SMEM_BYTES = (2*128*68 + 2*128*20) * 4;   // 90112

// mma GEMM config
static constexpr int KT  = 16;          // k-tile
static constexpr int NKT = D_ / KT;     // 48
static constexpr int PAD = 20;          // floats per smem row (16 used)
static constexpr int STAGE_F = 128*PAD;             // floats per tile-stage
static constexpr int GEMM_SMEM = 8 * STAGE_F * 4;   // 2 stages x 4 arrays = 81920B

// ---------------- mma.sync helpers ----------------
__device__ __forceinline__ uint32_t smem_u32(const void* p) {
    uint32_t a;
    asm("{ .reg .u64 t; cvta.to.shared.u64 t, %1; cvt.u32.u64 %0, t; }"
        : "=r"(a) : "l"(p));
    return a;
}
__device__ __forceinline__ float tf32_rna(float x) {
    uint32_t r; asm("cvt.rna.tf32.f32 %0, %1;" : "=r"(r) : "f"(x));
    return __uint_as_float(r);
}
__device__ __forceinline__ void ldsm4(uint32_t r[4], uint32_t a) {
    asm volatile("ldmatrix.sync.aligned.m8n8.x4.shared.b16 {%0,%1,%2,%3}, [%4];"
        : "=r"(r[0]), "=r"(r[1]), "=r"(r[2]), "=r"(r[3]) : "r"(a));
}
__device__ __forceinline__ void ldsm2(uint32_t r[2], uint32_t a) {
    asm volatile("ldmatrix.sync.aligned.m8n8.x2.shared.b16 {%0,%1}, [%2];"
        : "=r"(r[0]), "=r"(r[1]) : "r"(a));
}
__device__ __forceinline__ void mma8(float c[4], const uint32_t a[4],
                                     const uint32_t b[2]) {
    asm volatile(
        "mma.sync.aligned.m16n8k8.row.col.f32.tf32.tf32.f32 "
        "{%0,%1,%2,%3}, {%4,%5,%6,%7}, {%8,%9}, {%0,%1,%2,%3};"
        : "+f"(c[0]), "+f"(c[1]), "+f"(c[2]), "+f"(c[3])
        : "r"(a[0]), "r"(a[1]), "r"(a[2]), "r"(a[3]), "r"(b[0]), "r"(b[1]));
}
// split a float4 into tf32 hi / fp32 residual lo
__device__ __forceinline__ void split4(float4 v, float4& h, float4& l) {
    h.x = tf32_rna(v.x); l.x = v.x - h.x;
    h.y = tf32_rna(v.y); l.y = v.y - h.y;
    h.z = tf32_rna(v.z); l.z = v.z - h.z;
    h.w = tf32_rna(v.w); l.w = v.w - h.w;
}

// ---------------- device scratch ----------------
__device__ float g_q[(size_t)B_ * L_ * D_];
__device__ float g_k[(size_t)B_ * L_ * D_];
__device__ float g_v[(size_t)B_ * L_ * D_];
__device__ float g_w[(size_t)B_ * L_ * D_];

// ---------------- split-tf32 mma GEMM, double-buffered (verified) --------
__device__ __forceinline__ void mma_gemm_tile128(const float* __restrict__ A,
                                                 const float* __restrict__ W,
                                                 const float* __restrict__ bias,
                                                 float* __restrict__ C,
                                                 int m0, int n0)
{
    extern __shared__ float gsm[];
    float* Ah = gsm;                    // [2][128*PAD]
    float* Al = gsm + 2*STAGE_F;
    float* Bh = gsm + 4*STAGE_F;
    float* Bl = gsm + 6*STAGE_F;

    const int tid  = threadIdx.x;
    const int lane = tid & 31, wid = tid >> 5;
    const int wy = wid & 3, wx = wid >> 2;
    const int gid = lane >> 2, tig = lane & 3;

    const int rowL = tid >> 1, khL = (tid & 1) * 8;
    const float* Ap = A + (size_t)(m0 + rowL) * D_ + khL;
    const float* Wp = W + (size_t)(n0 + rowL) * D_ + khL;

    uint32_t aAh[2], aAl[2], aBh, aBl;
    {
        int r  = 32*wy + (lane & 7) + 8*((lane >> 3) & 1);
        int kc = 4 * (lane >> 4);
        aAh[0] = smem_u32(&Ah[r*PAD + kc]);
        aAh[1] = aAh[0] + 16*PAD*4;
        aAl[0] = smem_u32(&Al[r*PAD + kc]);
        aAl[1] = aAl[0] + 16*PAD*4;
        int rB  = 64*wx + (lane & 7);
        int kcB = 4 * ((lane >> 3) & 1);
        aBh = smem_u32(&Bh[rB*PAD + kcB]);
        aBl = smem_u32(&Bl[rB*PAD + kcB]);
    }

    float c[2][8][4] = {};

    float4 va0 = *(const float4*)(Ap);
    float4 va1 = *(const float4*)(Ap + 4);
    float4 vb0 = *(const float4*)(Wp);
    float4 vb1 = *(const float4*)(Wp + 4);
    {
        float4 h, l;
        split4(va0, h, l);
        *(float4*)&Ah[rowL*PAD + khL] = h; *(float4*)&Al[rowL*PAD + khL] = l;
        split4(va1, h, l);
        *(float4*)&Ah[rowL*PAD + khL + 4] = h; *(float4*)&Al[rowL*PAD + khL + 4] = l;
        split4(vb0, h, l);
        *(float4*)&Bh[rowL*PAD + khL] = h; *(float4*)&Bl[rowL*PAD + khL] = l;
        split4(vb1, h, l);
        *(float4*)&Bh[rowL*PAD + khL + 4] = h; *(float4*)&Bl[rowL*PAD + khL + 4] = l;
    }
    __syncthreads();

    for (int kt = 0; kt < NKT; kt++) {
        if (kt + 1 < NKT) {
            va0 = *(const float4*)(Ap + (kt+1)*KT);
            va1 = *(const float4*)(Ap + (kt+1)*KT + 4);
            vb0 = *(const float4*)(Wp + (kt+1)*KT);
            vb1 = *(const float4*)(Wp + (kt+1)*KT + 4);
        }
        const uint32_t sboff = (uint32_t)((kt & 1) * STAGE_F * 4);
        #pragma unroll
        for (int k8 = 0; k8 < 2; k8++) {
            const uint32_t ko = sboff + (uint32_t)(k8 * 32);
            uint32_t ah[2][4], al[2][4];
            ldsm4(ah[0], aAh[0] + ko);
            ldsm4(ah[1], aAh[1] + ko);
            ldsm4(al[0], aAl[0] + ko);
            ldsm4(al[1], aAl[1] + ko);
            #pragma unroll
            for (int nj = 0; nj < 8; nj++) {
                uint32_t bh[2], bl[2];
                ldsm2(bh, aBh + (uint32_t)(nj*8*PAD*4) + ko);
                ldsm2(bl, aBl + (uint32_t)(nj*8*PAD*4) + ko);
                #pragma unroll
                for (int mi = 0; mi < 2; mi++) {
                    mma8(c[mi][nj], ah[mi], bh);
                    mma8(c[mi][nj], ah[mi], bl);
                    mma8(c[mi][nj], al[mi], bh);
                }
            }
        }
        if (kt + 1 < NKT) {
            const int st = ((kt + 1) & 1) * STAGE_F;
            float4 h, l;
            split4(va0, h, l);
            *(float4*)&Ah[st + rowL*PAD + khL] = h; *(float4*)&Al[st + rowL*PAD + khL] = l;
            split4(va1, h, l);
            *(float4*)&Ah[st + rowL*PAD + khL + 4] = h; *(float4*)&Al[st + rowL*PAD + khL + 4] = l;
            split4(vb0, h, l);
            *(float4*)&Bh[st + rowL*PAD + khL] = h; *(float4*)&Bl[st + rowL*PAD + khL] = l;
            split4(vb1, h, l);
            *(float4*)&Bh[st + rowL*PAD + khL + 4] = h; *(float4*)&Bl[st + rowL*PAD + khL + 4] = l;
        }
        __syncthreads();
    }

    #pragma unroll
    for (int mi = 0; mi < 2; mi++) {
        const int r0 = m0 + 32*wy + 16*mi + gid;
        #pragma unroll
        for (int nj = 0; nj < 8; nj++) {
            const int cc = n0 + 64*wx + 8*nj + 2*tig;
            float2 v0 = make_float2(c[mi][nj][0], c[mi][nj][1]);
            float2 v1 = make_float2(c[mi][nj][2], c[mi][nj][3]);
            if (bias) {
                float bx = bias[cc], by = bias[cc+1];
                v0.x += bx; v0.y += by;
                v1.x += bx; v1.y += by;
            }
            *(float2*)&C[(size_t)r0 * D_ + cc]       = v0;
            *(float2*)&C[(size_t)(r0 + 8) * D_ + cc] = v1;
        }
    }
}

__global__ __launch_bounds__(256)
void mma_qkv_kernel(const float* __restrict__ Aq, const float* __restrict__ Ak,
                    const float* __restrict__ Av,
                    const float* __restrict__ Wq, const float* __restrict__ Wk,
                    const float* __restrict__ Wv,
                    float* __restrict__ Cq, float* __restrict__ Ck,
                    float* __restrict__ Cv)
{
    const int sel = blockIdx.x / 6;
    const int n0  = (blockIdx.x % 6) * 128;
    const int m0  = blockIdx.y * 128;
    const float* A = (sel == 0) ? Aq : (sel == 1) ? Ak : Av;
    const float* W = (sel == 0) ? Wq : (sel == 1) ? Wk : Wv;
    float*       C = (sel == 0) ? Cq : (sel == 1) ? Ck : Cv;
    mma_gemm_tile128(A, W, nullptr, C, m0, n0);
}

__global__ __launch_bounds__(256)
void mma_proj_kernel(const float* __restrict__ A, const float* __restrict__ W,
                     const float* __restrict__ bias, float* __restrict__ C)
{
    mma_gemm_tile128(A, W, bias, C, blockIdx.y * 128, blockIdx.x * 128);
}

// ---------------- attention: all-mma, online stats, 2 passes -------------
__global__ __launch_bounds__(256, 2)
void attn_kernel(const float* __restrict__ gq, const float* __restrict__ gk,
                 const float* __restrict__ gv,
                 const float* __restrict__ relk, const float* __restrict__ relv,
                 float* __restrict__ attn, float* __restrict__ gw)
{
    extern __shared__ float dsm[];
    // pass1 views
    float* Qh = dsm;                        // [128][68]
    float* Ql = dsm + 128*68;               // [128][68]
    float* Kh = dsm + 2*128*68;             // [128][20]
    float* Kl = dsm + 2*128*68 + 128*20;    // [128][20]
    // pass2 views (overlap)
    float* Es = dsm;                        // [128 m][132 k] row-major tf32 p
    float* Vs = dsm + 128*132;              // [64 k][68 d]  tf32 (half-chunk)

    __shared__ float sh_relk[7*HD_];
    __shared__ float sh_relv[7*HD_];
    __shared__ float sh_bias[TQ_*7];
    __shared__ float sh_m[TQ_];
    __shared__ float sh_t[TQ_];
    __shared__ float sh_madj[TQ_];
    __shared__ float sh_red[TQ_*2];
    __shared__ float sh_red2[TQ_*2];
    __shared__ float sh_S0[TQ_];
    __shared__ float sh_S6[TQ_];
    __shared__ float sh_pmid[TQ_*5];

    const int qq0 = blockIdx.x * TQ_;
    const int h   = blockIdx.y;
    const int b   = blockIdx.z;
    const int tid = threadIdx.x;
    const int lrow = tid >> 1;          // 0..127
    const int lk4  = (tid & 1) * 4;

    for (int i = tid; i < 7*HD_; i += 256) { sh_relk[i] = relk[i]; sh_relv[i] = relv[i]; }
    for (int i = tid; i < TQ_*5; i += 256) sh_pmid[i] = 0.f;
    if (tid < TQ_) { sh_m[tid] = -1e30f; sh_t[tid] = 0.f; }

    const float* qbase = gq + ((size_t)(b*L_ + qq0))*D_ + h*HD_;
    const float* kbase = gk + ((size_t)b*L_)*D_ + h*HD_;
    const float* vbase = gv + ((size_t)b*L_)*D_ + h*HD_;
    float* attn_base = attn + (((size_t)(b*H_ + h))*L_ + qq0) * L_;

    // ---- hoisted Q stage: split hi/lo into Qh/Ql[128][68] (once) ----
    {
        const int rowL = tid >> 1, khL = (tid & 1) * 8;
        #pragma unroll
        for (int t = 0; t < 4; t++) {
            int d = khL + 16*t;
            float4 q0 = *(const float4*)(qbase + (size_t)rowL*D_ + d);
            float4 q1 = *(const float4*)(qbase + (size_t)rowL*D_ + d + 4);
            float4 hh, ll;
            split4(q0, hh, ll);
            *(float4*)&Qh[rowL*68 + d] = hh; *(float4*)&Ql[rowL*68 + d] = ll;
            split4(q1, hh, ll);
            *(float4*)&Qh[rowL*68 + d + 4] = hh; *(float4*)&Ql[rowL*68 + d + 4] = ll;
        }
    }
    __syncthreads();   // relk loaded + Q staged + m/t init

    // ---- rel-k bias: bias[m][r] = Q[m] . rel_k[r] ----
    for (int idx = tid; idx < TQ_*7; idx += 256) {
        int m = idx / 7, rr = idx % 7;
        float s = 0.f;
        #pragma unroll
        for (int d = 0; d < HD_; d++)
            s = fmaf(qbase[(size_t)m*D_ + d], sh_relk[rr*HD_ + d], s);
        sh_bias[idx] = s;
    }
    __syncthreads();

    // ================= pass 1: logits via split-tf32 mma + online (m,t) ==
    const int lane = tid & 31, wid = tid >> 5;
    const int wy = wid & 3, wx = wid >> 2;
    const int gid = lane >> 2, tig = lane & 3;
    const int rowL = tid >> 1, khL = (tid & 1) * 8;

    uint32_t aQh[2], aQl[2], aKh, aKl;
    {
        int r  = 32*wy + (lane & 7) + 8*((lane >> 3) & 1);
        int kc = 4 * (lane >> 4);
        aQh[0] = smem_u32(&Qh[r*68 + kc]);
        aQh[1] = aQh[0] + 16*68*4;
        aQl[0] = smem_u32(&Ql[r*68 + kc]);
        aQl[1] = aQl[0] + 16*68*4;
        int rB  = 64*wx + (lane & 7);
        int kcB = 4 * ((lane >> 3) & 1);
        aKh = smem_u32(&Kh[rB*20 + kcB]);
        aKl = smem_u32(&Kl[rB*20 + kcB]);
    }

    for (int kc = 0; kc < NCH_; kc++) {
        const int k0 = kc * TK_;
        float c[2][8][4] = {};
        #pragma unroll
        for (int kt = 0; kt < 4; kt++) {
            // stage K d16-slice, split hi/lo
            {
                float4 kv0 = *(const float4*)(kbase + (size_t)(k0 + rowL)*D_ + kt*16 + khL);
                float4 kv1 = *(const float4*)(kbase + (size_t)(k0 + rowL)*D_ + kt*16 + khL + 4);
                float4 hh, ll;
                split4(kv0, hh, ll);
                *(float4*)&Kh[rowL*20 + khL] = hh; *(float4*)&Kl[rowL*20 + khL] = ll;
                split4(kv1, hh, ll);
                *(float4*)&Kh[rowL*20 + khL + 4] = hh; *(float4*)&Kl[rowL*20 + khL + 4] = ll;
            }
            __syncthreads();
            #pragma unroll
            for (int k8 = 0; k8 < 2; k8++) {
                const uint32_t koQ = (uint32_t)((kt*16 + k8*8) * 4);
                const uint32_t koK = (uint32_t)(k8 * 32);
                uint32_t ah[2][4], al[2][4];
                ldsm4(ah[0], aQh[0] + koQ);
                ldsm4(ah[1], aQh[1] + koQ);
                ldsm4(al[0], aQl[0] + koQ);
                ldsm4(al[1], aQl[1] + koQ);
                #pragma unroll
                for (int nj = 0; nj < 8; nj++) {
                    uint32_t bh[2], bl[2];
                    ldsm2(bh, aKh + (uint32_t)(nj*8*20*4) + koK);
                    ldsm2(bl, aKl + (uint32_t)(nj*8*20*4) + koK);
                    #pragma unroll
                    for (int mi = 0; mi < 2; mi++) {
                        mma8(c[mi][nj], ah[mi], bh);
                        mma8(c[mi][nj], ah[mi], bl);
                        mma8(c[mi][nj], al[mi], bh);
                    }
                }
            }
            __syncthreads();
        }
        // ---- epilogue step1: s = 8*(c + bias) into c-frags, store S, cmax
        float cmax[2][2];
        #pragma unroll
        for (int mi = 0; mi < 2; mi++) {
            #pragma unroll
            for (int half = 0; half < 2; half++) {
                const int m  = 32*wy + 16*mi + 8*half + gid;
                const int qg = qq0 + m;
                const float* brow = &sh_bias[m*7];
                float mx = -1e30f;
                #pragma unroll
                for (int nj = 0; nj < 8; nj++) {
                    const int kg = k0 + 64*wx + 8*nj + 2*tig;
                    int d0 = kg - qg, d1 = d0 + 1;
                    int r0 = d0 < -3 ? 0 : (d0 > 3 ? 6 : d0 + 3);
                    int r1 = d1 < -3 ? 0 : (d1 > 3 ? 6 : d1 + 3);
                    float s0 = 8.f * (c[mi][nj][2*half]     + brow[r0]);
                    float s1 = 8.f * (c[mi][nj][2*half + 1] + brow[r1]);
                    c[mi][nj][2*half]     = s0;
                    c[mi][nj][2*half + 1] = s1;
                    mx = fmaxf(mx, fmaxf(s0, s1));
                    *(float2*)&attn_base[(size_t)m*L_ + kg] = make_float2(s0, s1);
                }
                cmax[mi][half] = mx;
            }
        }
        // ---- step2: chunk rowmax reduce (tig shfl + cross-wx smem) ----
        #pragma unroll
        for (int mi = 0; mi < 2; mi++)
            #pragma unroll
            for (int half = 0; half < 2; half++) {
                float v = cmax[mi][half];
                v = fmaxf(v, __shfl_xor_sync(0xffffffffu, v, 1));
                v = fmaxf(v, __shfl_xor_sync(0xffffffffu, v, 2));
                if (tig == 0)
                    sh_red[(32*wy + 16*mi + 8*half + gid)*2 + wx] = v;
            }
        __syncthreads();
        // ---- step3: mnew + local exp-sums ----
        float mnewr[2][2], lsum[2][2];
        #pragma unroll
        for (int mi = 0; mi < 2; mi++) {
            #pragma unroll
            for (int half = 0; half < 2; half++) {
                const int row = 32*wy + 16*mi + 8*half + gid;
                float m_ch = fmaxf(sh_red[row*2], sh_red[row*2 + 1]);
                float mnew = fmaxf(sh_m[row], m_ch);
                mnewr[mi][half] = mnew;
                float ls = 0.f;
                #pragma unroll
                for (int nj = 0; nj < 8; nj++)
                    ls += __expf(c[mi][nj][2*half] - mnew)
                        + __expf(c[mi][nj][2*half + 1] - mnew);
                lsum[mi][half] = ls;
            }
        }
        // ---- step4: chunk sum reduce ----
        #pragma unroll
        for (int mi = 0; mi < 2; mi++)
            #pragma unroll
            for (int half = 0; half < 2; half++) {
                float v = lsum[mi][half];
                v += __shfl_xor_sync(0xffffffffu, v, 1);
                v += __shfl_xor_sync(0xffffffffu, v, 2);
                if (tig == 0)
                    sh_red2[(32*wy + 16*mi + 8*half + gid)*2 + wx] = v;
            }
        __syncthreads();
        // ---- step5: one owner per row updates (m, t) ----
        if (wx == 0 && tig == 0) {
            #pragma unroll
            for (int mi = 0; mi < 2; mi++)
                #pragma unroll
                for (int half = 0; half < 2; half++) {
                    const int row = 32*wy + 16*mi + 8*half + gid;
                    float mnew = mnewr[mi][half];
                    float told = sh_t[row], mold = sh_m[row];
                    sh_t[row] = told * __expf(mold - mnew)
                              + sh_red2[row*2] + sh_red2[row*2 + 1];
                    sh_m[row] = mnew;
                }
        }
        // (next-chunk kt-loop barriers order step5 vs subsequent reads)
    }

    __syncthreads();
    if (tid < TQ_) sh_madj[tid] = sh_m[tid] + __logf(sh_t[tid]);
    __syncthreads();

    // ================= pass 2: normalized p + PV via mma + p writeback ===
    const int m2   = lrow;
    const int c0   = lk4;
    const int qg2  = qq0 + m2;
    const float rm2 = sh_madj[m2];      // p = exp(s - rm2) is normalized

    uint32_t aE[2];
    {
        int r  = 32*wy + (lane & 7) + 8*((lane >> 3) & 1);
        int kcc = 4 * (lane >> 4);
        aE[0] = smem_u32(&Es[r*132 + kcc]);
        aE[1] = aE[0] + 16*132*4;
    }
    const int dbase = 32*wx;
    const int kvrow = tid >> 2, dv0 = (tid & 3) * 16;

    float s0sum = 0.f, s6sum = 0.f;
    float c2[2][4][4] = {};

    for (int kc = 0; kc < NCH_; kc++) {
        const int k0 = kc * TK_;
        // ---- stage V half0, tf32-rounded ----
        #pragma unroll
        for (int t = 0; t < 4; t++) {
            float4 v = *(const float4*)(vbase + (size_t)(k0 + kvrow)*D_ + dv0 + 4*t);
            v.x = tf32_rna(v.x); v.y = tf32_rna(v.y);
            v.z = tf32_rna(v.z); v.w = tf32_rna(v.w);
            *(float4*)&Vs[kvrow*68 + dv0 + 4*t] = v;
        }
        // ---- exp stage: p (normalized), buckets, tf32 p to Es ----
        #pragma unroll
        for (int r = 0; r < 16; r++) {
            int c = c0 + 8*r;
            float4 sv = *(const float4*)(attn_base + (size_t)m2*L_ + k0 + c);
            float e0 = __expf(sv.x - rm2);
            float e1 = __expf(sv.y - rm2);
            float e2 = __expf(sv.z - rm2);
            float e3 = __expf(sv.w - rm2);
            #pragma unroll
            for (int j = 0; j < 4; j++) {
                float e = (j == 0) ? e0 : (j == 1) ? e1 : (j == 2) ? e2 : e3;
                int dlt = k0 + c + j - qg2;
                if (dlt <= -3)      s0sum += e;
                else if (dlt >= 3)  s6sum += e;
                else                sh_pmid[m2*5 + dlt + 2] = e;
            }
            float4 er = make_float4(tf32_rna(e0), tf32_rna(e1), tf32_rna(e2), tf32_rna(e3));
            *(float4*)&Es[m2*132 + c] = er;
        }
        // ---- p writeback: own Es row -> attn (separate tight loop) ----
        #pragma unroll
        for (int r = 0; r < 16; r++) {
            int c = c0 + 8*r;
            float4 pv4 = *(const float4*)&Es[m2*132 + c];
            *(float4*)(attn_base + (size_t)m2*L_ + k0 + c) = pv4;
        }
        __syncthreads();

        // ---- PV mma half0 ----
        #pragma unroll
        for (int k8 = 0; k8 < 8; k8++) {
            const uint32_t ko = (uint32_t)(k8 * 32);
            uint32_t a[2][4];
            ldsm4(a[0], aE[0] + ko);
            ldsm4(a[1], aE[1] + ko);
            #pragma unroll
            for (int nj = 0; nj < 4; nj++) {
                uint32_t bb[2];
                bb[0] = __float_as_uint(Vs[(k8*8 + tig    )*68 + dbase + 8*nj + gid]);
                bb[1] = __float_as_uint(Vs[(k8*8 + tig + 4)*68 + dbase + 8*nj + gid]);
                mma8(c2[0][nj], a[0], bb);
                mma8(c2[1][nj], a[1], bb);
            }
        }
        __syncthreads();
        // ---- stage V half1 ----
        #pragma unroll
        for (int t = 0; t < 4; t++) {
            float4 v = *(const float4*)(vbase + (size_t)(k0 + 64 + kvrow)*D_ + dv0 + 4*t);
            v.x = tf32_rna(v.x); v.y = tf32_rna(v.y);
            v.z = tf32_rna(v.z); v.w = tf32_rna(v.w);
            *(float4*)&Vs[kvrow*68 + dv0 + 4*t] = v;
        }
        __syncthreads();
        // ---- PV mma half1 ----
        #pragma unroll
        for (int k8 = 0; k8 < 8; k8++) {
            const uint32_t ko = (uint32_t)((64 + k8*8) * 4);
            uint32_t a[2][4];
            ldsm4(a[0], aE[0] + ko);
            ldsm4(a[1], aE[1] + ko);
            #pragma unroll
            for (int nj = 0; nj < 4; nj++) {
                uint32_t bb[2];
                bb[0] = __float_as_uint(Vs[(k8*8 + tig    )*68 + dbase + 8*nj + gid]);
                bb[1] = __float_as_uint(Vs[(k8*8 + tig + 4)*68 + dbase + 8*nj + gid]);
                mma8(c2[0][nj], a[0], bb);
                mma8(c2[1][nj], a[1], bb);
            }
        }
        __syncthreads();
    }

    // ---- bucket pair reduce (two threads per row) ----
    s0sum += __shfl_xor_sync(0xffffffffu, s0sum, 1);
    s6sum += __shfl_xor_sync(0xffffffffu, s6sum, 1);
    if ((tid & 1) == 0) { sh_S0[m2] = s0sum; sh_S6[m2] = s6sum; }
    __syncthreads();

    // ---- w = PV + w2 (already normalized) -> gw [B,L,H,hd] ----
    {
        float* wbase = gw + ((size_t)(b*L_ + qq0))*D_ + h*HD_;
        #pragma unroll
        for (int mi = 0; mi < 2; mi++) {
            #pragma unroll
            for (int half = 0; half < 2; half++) {
                const int m = 32*wy + 16*mi + 8*half + gid;
                float S0 = sh_S0[m];
                float S6 = sh_S6[m];
                float mids[5];
                #pragma unroll
                for (int rr = 0; rr < 5; rr++) mids[rr] = sh_pmid[m*5 + rr];
                #pragma unroll
                for (int nj = 0; nj < 4; nj++) {
                    const int d0c = 32*wx + 8*nj + 2*tig;
                    float w2a = S0 * sh_relv[d0c]     + S6 * sh_relv[6*HD_ + d0c];
                    float w2b = S0 * sh_relv[d0c + 1] + S6 * sh_relv[6*HD_ + d0c + 1];
                    #pragma unroll
                    for (int rr = 0; rr < 5; rr++) {
                        w2a = fmaf(mids[rr], sh_relv[(rr+1)*HD_ + d0c],     w2a);
                        w2b = fmaf(mids[rr], sh_relv[(rr+1)*HD_ + d0c + 1], w2b);
                    }
                    float2 o;
                    o.x = c2[mi][nj][2*half]     + w2a;
                    o.y = c2[mi][nj][2*half + 1] + w2b;
                    *(float2*)(wbase + (size_t)m*D_ + d0c) = o;
                }
            }
        }
    }
}

// ---------------- launch ----------------
extern "C" void kernel_launch(void* const* d_in, const int* in_sizes, int n_in,
                              void* d_out, int out_size)
{
    const float* query  = (const float*)d_in[0];
    const float* key    = (const float*)d_in[1];
    const float* value  = (const float*)d_in[2];
    const float* Wq     = (const float*)d_in[3];
    const float* Wk     = (const float*)d_in[4];
    const float* Wv     = (const float*)d_in[5];
    const float* Wproj  = (const float*)d_in[6];
    const float* b_proj = (const float*)d_in[7];
    const float* relk   = (const float*)d_in[8];
    const float* relv   = (const float*)d_in[9];

    float* out  = (float*)d_out;
    float* attn = out + (size_t)B_ * L_ * D_;   // x first, then attn

    float *gq, *gk, *gv, *gw;
    cudaGetSymbolAddress((void**)&gq, g_q);
    cudaGetSymbolAddress((void**)&gk, g_k);
    cudaGetSymbolAddress((void**)&gv, g_v);
    cudaGetSymbolAddress((void**)&gw, g_w);

    cudaFuncSetAttribute(attn_kernel, cudaFuncAttributeMaxDynamicSharedMemorySize,
                         DYN_SMEM_BYTES);
    cudaFuncSetAttribute(mma_qkv_kernel, cudaFuncAttributeMaxDynamicSharedMemorySize,
                         GEMM_SMEM);
    cudaFuncSetAttribute(mma_proj_kernel, cudaFuncAttributeMaxDynamicSharedMemorySize,
                         GEMM_SMEM);

    mma_qkv_kernel<<<dim3(18, 32), 256, GEMM_SMEM>>>(query, key, value,
                                                     Wq, Wk, Wv, gq, gk, gv);

    attn_kernel<<<dim3(L_/TQ_, H_, B_), 256, DYN_SMEM_BYTES>>>(
        gq, gk, gv, relk, relv, attn, gw);

    mma_proj_kernel<<<dim3(6, 32), 256, GEMM_SMEM>>>(gw, Wproj, b_proj, out);
}